// round 1
// baseline (speedup 1.0000x reference)
#include <cuda_runtime.h>

// ---------------- problem constants ----------------
#define B_  64
#define N_  64
#define VF_ 32
#define EF_ 16
#define D_  128
#define LN_ 4

constexpr int NV  = B_ * N_;        // 4096 vertices
constexpr int NE  = B_ * N_ * N_;   // 262144 edges
constexpr int BNC = N_ * VF_;       // 2048 bn_flat columns

// ---------------- device scratch (no allocation allowed) ----------------
__device__ float g_v0[NV * VF_];
__device__ float g_v1[NV * D_];
__device__ float g_v2[NV * D_];
__device__ float g_ev[NV * D_];
__device__ float g_pve[NV * D_];
__device__ float g_eA[(size_t)NE * D_];   // current e   (128 MB)
__device__ float g_eB[(size_t)NE * D_];   // e_out scratch (128 MB)
__device__ float g_ev3[NV];
__device__ float g_pve3[NV];

// ---------------- bn_flat: BatchNorm1d(N*VF) over batch dim ----------------
__global__ void bn_flat_kernel(const float* __restrict__ v,
                               const float* __restrict__ g,
                               const float* __restrict__ b,
                               float* __restrict__ out) {
    int c = blockIdx.x * blockDim.x + threadIdx.x;
    if (c >= BNC) return;
    float s = 0.f, s2 = 0.f;
    for (int r = 0; r < B_; r++) {
        float x = v[r * BNC + c];
        s += x; s2 += x * x;
    }
    float mu  = s * (1.f / B_);
    float var = s2 * (1.f / B_) - mu * mu;
    float sc  = rsqrtf(var + 1e-5f) * g[c];
    float bb  = b[c] - mu * sc;
    for (int r = 0; r < B_; r++)
        out[r * BNC + c] = v[r * BNC + c] * sc + bb;
}

// ---------------- small row GEMM: out[r,d] = A[r,:]@W + bias ----------------
template <int DIN>
__global__ void rows_gemm_bias(const float* __restrict__ A,
                               const float* __restrict__ W,
                               const float* __restrict__ bias,
                               float* __restrict__ out) {
    __shared__ float sA[16 * DIN];
    int r0 = blockIdx.x * 16;
    for (int idx = threadIdx.x; idx < 16 * DIN; idx += 128)
        sA[idx] = A[r0 * DIN + idx];
    __syncthreads();
    int d = threadIdx.x;
    float acc[16];
    float b0 = bias[d];
#pragma unroll
    for (int r = 0; r < 16; r++) acc[r] = b0;
    for (int k = 0; k < DIN; k++) {
        float w = W[k * D_ + d];
#pragma unroll
        for (int r = 0; r < 16; r++) acc[r] += sA[r * DIN + k] * w;
    }
#pragma unroll
    for (int r = 0; r < 16; r++) out[(r0 + r) * D_ + d] = acc[r];
}

// ---------------- fused edge layer: 128x128 tile GEMM, BK=8 ----------------
// e_out[r,d] = act( E_in[r,:]@W + eb[d] + ev[b,i,d] + ev[b,j,d] )
// if RESID: E_res[r,d] = e_out[r,d] + E_in[r,d]   (DIN==128, in-place safe:
// each block reads/writes only its own 128 rows)
template <int DIN, bool RELU, bool RESID>
__global__ void __launch_bounds__(256) e_layer_kernel(
    const float* Ein, const float* __restrict__ W,
    const float* __restrict__ eb, const float* __restrict__ ev,
    float* __restrict__ Eout, float* Eres) {
    __shared__ float As[8][132];   // padded: conflict-free transposed stores
    __shared__ float Bs[8][128];
    const int tid  = threadIdx.x;
    const int row0 = blockIdx.x * 128;
    const int tx = tid & 15;
    const int ty = tid >> 4;

    float acc[8][8];
#pragma unroll
    for (int i = 0; i < 8; i++)
#pragma unroll
        for (int j = 0; j < 8; j++) acc[i][j] = 0.f;

    const int lr = tid >> 1;        // A load: row
    const int lh = (tid & 1) * 4;   // A load: k offset (0/4)
    const int bk = tid >> 5;        // B load: k row
    const int bc = (tid & 31) * 4;  // B load: col

    for (int k0 = 0; k0 < DIN; k0 += 8) {
        float4 a4 = *(const float4*)(Ein + (size_t)(row0 + lr) * DIN + k0 + lh);
        As[lh + 0][lr] = a4.x; As[lh + 1][lr] = a4.y;
        As[lh + 2][lr] = a4.z; As[lh + 3][lr] = a4.w;
        float4 b4 = *(const float4*)(W + (k0 + bk) * D_ + bc);
        *(float4*)&Bs[bk][bc] = b4;
        __syncthreads();
#pragma unroll
        for (int k = 0; k < 8; k++) {
            float4 a0 = *(const float4*)&As[k][ty * 8];
            float4 a1 = *(const float4*)&As[k][ty * 8 + 4];
            float4 b0 = *(const float4*)&Bs[k][tx * 8];
            float4 b1 = *(const float4*)&Bs[k][tx * 8 + 4];
            float av[8] = {a0.x, a0.y, a0.z, a0.w, a1.x, a1.y, a1.z, a1.w};
            float bv[8] = {b0.x, b0.y, b0.z, b0.w, b1.x, b1.y, b1.z, b1.w};
#pragma unroll
            for (int i = 0; i < 8; i++)
#pragma unroll
                for (int j = 0; j < 8; j++) acc[i][j] += av[i] * bv[j];
        }
        __syncthreads();
    }

    // epilogue: bias + ev broadcasts + relu + (residual), vectorized stores
#pragma unroll
    for (int i = 0; i < 8; i++) {
        int r  = row0 + ty * 8 + i;
        int b  = r >> 12;
        int ii = (r >> 6) & 63;
        int jj = r & 63;
        const float* evi = ev + (b * N_ + ii) * D_;
        const float* evj = ev + (b * N_ + jj) * D_;
        float vals[8];
#pragma unroll
        for (int j = 0; j < 8; j++) {
            int d = tx * 8 + j;
            float val = acc[i][j] + eb[d] + evi[d] + evj[d];
            if (RELU) val = fmaxf(val, 0.f);
            vals[j] = val;
        }
        size_t off = (size_t)r * D_ + tx * 8;
        *(float4*)(Eout + off)     = make_float4(vals[0], vals[1], vals[2], vals[3]);
        *(float4*)(Eout + off + 4) = make_float4(vals[4], vals[5], vals[6], vals[7]);
        if (RESID) {
            float4 o0 = *(const float4*)(Ein + off);
            float4 o1 = *(const float4*)(Ein + off + 4);
            *(float4*)(Eres + off)     = make_float4(vals[0] + o0.x, vals[1] + o0.y,
                                                     vals[2] + o0.z, vals[3] + o0.w);
            *(float4*)(Eres + off + 4) = make_float4(vals[4] + o1.x, vals[5] + o1.y,
                                                     vals[6] + o1.z, vals[7] + o1.w);
        }
    }
}

// ---------------- per_v_e[b,j,d] = sum_i e_out[b,i,j,d] ----------------
__global__ void sum_i_kernel(const float* __restrict__ E, float* __restrict__ pve) {
    int idx = blockIdx.x * 256 + threadIdx.x;   // NV*D_ threads
    int d  = idx & 127;
    int bj = idx >> 7;
    int b  = bj >> 6, j = bj & 63;
    const float* base = E + (size_t)b * (N_ * N_ * D_) + j * D_ + d;
    float s = 0.f;
#pragma unroll 8
    for (int i = 0; i < N_; i++) s += base[(size_t)i * (N_ * D_)];
    pve[idx] = s;
}

// ---------------- vertex layer: concat([pve, vin]) @ vW + vb ----------------
template <int DVIN, bool RELU, bool RESID>
__global__ void v_layer_kernel(const float* __restrict__ pve,
                               const float* __restrict__ vin,
                               const float* __restrict__ vW,   // [(D_+DVIN), D_]
                               const float* __restrict__ vb,
                               const float* __restrict__ vres,
                               float* __restrict__ vout) {
    __shared__ float sP[16 * D_];
    __shared__ float sV[16 * DVIN];
    int r0 = blockIdx.x * 16;
    for (int idx = threadIdx.x; idx < 16 * D_; idx += 128) sP[idx] = pve[r0 * D_ + idx];
    for (int idx = threadIdx.x; idx < 16 * DVIN; idx += 128) sV[idx] = vin[r0 * DVIN + idx];
    __syncthreads();
    int d = threadIdx.x;
    float acc[16];
    float b0 = vb[d];
#pragma unroll
    for (int r = 0; r < 16; r++) acc[r] = b0;
    for (int k = 0; k < D_; k++) {
        float w = vW[k * D_ + d];
#pragma unroll
        for (int r = 0; r < 16; r++) acc[r] += sP[r * D_ + k] * w;
    }
    for (int k = 0; k < DVIN; k++) {
        float w = vW[(D_ + k) * D_ + d];
#pragma unroll
        for (int r = 0; r < 16; r++) acc[r] += sV[r * DVIN + k] * w;
    }
#pragma unroll
    for (int r = 0; r < 16; r++) {
        float val = acc[r];
        if (RELU) val = fmaxf(val, 0.f);
        if (RESID) val += vres[(r0 + r) * D_ + d];
        vout[(r0 + r) * D_ + d] = val;
    }
}

// ---------------- bn_inner: channels = n axis, stats over (B, D), eps=128 ----
__global__ void bn_inner_kernel(float* __restrict__ v,
                                const float* __restrict__ g,
                                const float* __restrict__ bb) {
    __shared__ float red[256], red2[256];
    int n = blockIdx.x;
    float s = 0.f, s2 = 0.f;
    for (int idx = threadIdx.x; idx < B_ * D_; idx += 256) {
        int batch = idx >> 7, d = idx & 127;
        float x = v[(batch * N_ + n) * D_ + d];
        s += x; s2 += x * x;
    }
    red[threadIdx.x] = s; red2[threadIdx.x] = s2;
    __syncthreads();
    for (int off = 128; off; off >>= 1) {
        if (threadIdx.x < off) {
            red[threadIdx.x]  += red[threadIdx.x + off];
            red2[threadIdx.x] += red2[threadIdx.x + off];
        }
        __syncthreads();
    }
    float mu  = red[0] * (1.f / (B_ * D_));
    float var = red2[0] * (1.f / (B_ * D_)) - mu * mu;
    float A   = rsqrtf(var + 128.f) * g[n];
    float Bc  = bb[n] - mu * A;
    for (int idx = threadIdx.x; idx < B_ * D_; idx += 256) {
        int batch = idx >> 7, d = idx & 127;
        int off = (batch * N_ + n) * D_ + d;
        v[off] = v[off] * A + Bc;
    }
}

// ---------------- final layer (output dims = 1) ----------------
__global__ void ev3_kernel(const float* __restrict__ v, const float* __restrict__ W,
                           const float* __restrict__ bias, float* __restrict__ out) {
    int gt = blockIdx.x * blockDim.x + threadIdx.x;
    int warp = gt >> 5, lane = gt & 31;
    if (warp >= NV) return;
    const float* row = v + warp * D_;
    float s = 0.f;
    for (int k = lane; k < D_; k += 32) s += row[k] * W[k];
    for (int o = 16; o; o >>= 1) s += __shfl_xor_sync(0xffffffffu, s, o);
    if (lane == 0) out[warp] = s + bias[0];
}

__global__ void e3_kernel(const float* __restrict__ e, const float* __restrict__ W,
                          const float* __restrict__ bias, const float* __restrict__ ev3,
                          float* __restrict__ out) {
    int gt = blockIdx.x * blockDim.x + threadIdx.x;
    int warp = gt >> 5, lane = gt & 31;
    if (warp >= NE) return;
    const float* row = e + (size_t)warp * D_;
    float s = 0.f;
    for (int k = lane; k < D_; k += 32) s += row[k] * W[k];
    for (int o = 16; o; o >>= 1) s += __shfl_xor_sync(0xffffffffu, s, o);
    if (lane == 0) {
        int b = warp >> 12, ii = (warp >> 6) & 63, jj = warp & 63;
        out[warp] = s + bias[0] + ev3[b * 64 + jj] + ev3[b * 64 + ii];
    }
}

__global__ void pve3_kernel(const float* __restrict__ e3, float* __restrict__ pve) {
    int idx = blockIdx.x * blockDim.x + threadIdx.x;
    if (idx >= NV) return;
    int b = idx >> 6, j = idx & 63;
    float s = 0.f;
#pragma unroll 8
    for (int i = 0; i < N_; i++) s += e3[(b * 64 + i) * 64 + j];
    pve[idx] = s;
}

__global__ void v3_kernel(const float* __restrict__ v, const float* __restrict__ pve3,
                          const float* __restrict__ W, const float* __restrict__ bias,
                          float* __restrict__ out) {
    int gt = blockIdx.x * blockDim.x + threadIdx.x;
    int warp = gt >> 5, lane = gt & 31;
    if (warp >= NV) return;
    const float* row = v + warp * D_;
    float s = 0.f;
    for (int k = lane; k < D_; k += 32) s += row[k] * W[1 + k];
    for (int o = 16; o; o >>= 1) s += __shfl_xor_sync(0xffffffffu, s, o);
    if (lane == 0) out[warp] = s + pve3[warp] * W[0] + bias[0];
}

// ---------------- host orchestration ----------------
extern "C" void kernel_launch(void* const* d_in, const int* in_sizes, int n_in,
                              void* d_out, int out_size) {
    const float* v_in    = (const float*)d_in[0];
    const float* e_in    = (const float*)d_in[1];
    const float* bn_in_g = (const float*)d_in[2];
    const float* bn_in_b = (const float*)d_in[3];
    const float* g1_evW  = (const float*)d_in[4];
    const float* g1_evb  = (const float*)d_in[5];
    const float* g1_eW   = (const float*)d_in[6];
    const float* g1_eb   = (const float*)d_in[7];
    const float* g1_vW   = (const float*)d_in[8];
    const float* g1_vb   = (const float*)d_in[9];
    const float* inn_evW = (const float*)d_in[10];
    const float* inn_evb = (const float*)d_in[11];
    const float* inn_eW  = (const float*)d_in[12];
    const float* inn_eb  = (const float*)d_in[13];
    const float* inn_vW  = (const float*)d_in[14];
    const float* inn_vb  = (const float*)d_in[15];
    const float* bn_g    = (const float*)d_in[16];
    const float* bn_b    = (const float*)d_in[17];
    const float* g3_evW  = (const float*)d_in[18];
    const float* g3_evb  = (const float*)d_in[19];
    const float* g3_eW   = (const float*)d_in[20];
    const float* g3_eb   = (const float*)d_in[21];
    const float* g3_vW   = (const float*)d_in[22];
    const float* g3_vb   = (const float*)d_in[23];
    float* out = (float*)d_out;

    float *pv0, *pv1, *pv2, *pev, *ppve, *peA, *peB, *pev3, *ppve3;
    cudaGetSymbolAddress((void**)&pv0,  g_v0);
    cudaGetSymbolAddress((void**)&pv1,  g_v1);
    cudaGetSymbolAddress((void**)&pv2,  g_v2);
    cudaGetSymbolAddress((void**)&pev,  g_ev);
    cudaGetSymbolAddress((void**)&ppve, g_pve);
    cudaGetSymbolAddress((void**)&peA,  g_eA);
    cudaGetSymbolAddress((void**)&peB,  g_eB);
    cudaGetSymbolAddress((void**)&pev3, g_ev3);
    cudaGetSymbolAddress((void**)&ppve3, g_pve3);

    // input BN
    bn_flat_kernel<<<(BNC + 255) / 256, 256>>>(v_in, bn_in_g, bn_in_b, pv0);

    // layer 1
    rows_gemm_bias<VF_><<<NV / 16, 128>>>(pv0, g1_evW, g1_evb, pev);
    e_layer_kernel<EF_, true, false><<<NE / 128, 256>>>(e_in, g1_eW, g1_eb, pev, peA, nullptr);
    sum_i_kernel<<<NV * D_ / 256, 256>>>(peA, ppve);
    v_layer_kernel<VF_, true, false><<<NV / 16, 128>>>(ppve, pv0, g1_vW, g1_vb, nullptr, pv1);

    // inner residual layers
    float* vcur = pv1;
    float* vnxt = pv2;
    for (int l = 0; l < LN_; l++) {
        rows_gemm_bias<D_><<<NV / 16, 128>>>(vcur, inn_evW + l * D_ * D_, inn_evb + l * D_, pev);
        e_layer_kernel<D_, true, true><<<NE / 128, 256>>>(peA, inn_eW + l * D_ * D_,
                                                          inn_eb + l * D_, pev, peB, peA);
        sum_i_kernel<<<NV * D_ / 256, 256>>>(peB, ppve);
        v_layer_kernel<D_, true, true><<<NV / 16, 128>>>(ppve, vcur, inn_vW + l * (2 * D_) * D_,
                                                         inn_vb + l * D_, vcur, vnxt);
        bn_inner_kernel<<<N_, 256>>>(vnxt, bn_g + l * N_, bn_b + l * N_);
        float* t = vcur; vcur = vnxt; vnxt = t;
    }

    // final layer (no relu), write directly into d_out: v [NV] then e [NE]
    ev3_kernel<<<NV * 32 / 256, 256>>>(vcur, g3_evW, g3_evb, pev3);
    e3_kernel<<<NE * 32 / 256, 256>>>(peA, g3_eW, g3_eb, pev3, out + NV);
    pve3_kernel<<<(NV + 255) / 256, 256>>>(out + NV, ppve3);
    v3_kernel<<<NV * 32 / 256, 256>>>(vcur, ppve3, g3_vW, g3_vb, out);
}

// round 2
// speedup vs baseline: 1.1327x; 1.1327x over previous
#include <cuda_runtime.h>

// ---------------- problem constants ----------------
#define B_  64
#define N_  64
#define VF_ 32
#define EF_ 16
#define D_  128
#define LN_ 4

constexpr int NV  = B_ * N_;        // 4096 vertices
constexpr int NE  = B_ * N_ * N_;   // 262144 edges
constexpr int BNC = N_ * VF_;       // 2048 bn_flat columns

// ---------------- device scratch (no allocation allowed) ----------------
__device__ float g_v0[NV * VF_];
__device__ float g_v1[NV * D_];
__device__ float g_v2[NV * D_];
__device__ float g_ev[NV * D_];
__device__ float g_pve[NV * D_];
__device__ float g_S[NV * D_];            // running sum_i of residual e-state
__device__ float g_eA[(size_t)NE * D_];   // e residual state (128 MB), updated in place
__device__ float g_ev3[NV];
__device__ float g_pve3[NV];

// ---------------- helpers ----------------
__device__ __forceinline__ float tf32r(float x) {
    unsigned u;
    asm("cvt.rna.tf32.f32 %0, %1;" : "=r"(u) : "f"(x));
    return __uint_as_float(u);
}

__device__ __forceinline__ void mma8(float* c, const unsigned* a, unsigned b0, unsigned b1) {
    asm volatile("mma.sync.aligned.m16n8k8.row.col.f32.tf32.tf32.f32 "
                 "{%0,%1,%2,%3}, {%4,%5,%6,%7}, {%8,%9}, {%0,%1,%2,%3};\n"
                 : "+f"(c[0]), "+f"(c[1]), "+f"(c[2]), "+f"(c[3])
                 : "r"(a[0]), "r"(a[1]), "r"(a[2]), "r"(a[3]), "r"(b0), "r"(b1));
}

// ---------------- bn_flat ----------------
__global__ void bn_flat_kernel(const float* __restrict__ v,
                               const float* __restrict__ g,
                               const float* __restrict__ b,
                               float* __restrict__ out) {
    int c = blockIdx.x * blockDim.x + threadIdx.x;
    if (c >= BNC) return;
    float s = 0.f, s2 = 0.f;
    for (int r = 0; r < B_; r++) {
        float x = v[r * BNC + c];
        s += x; s2 += x * x;
    }
    float mu  = s * (1.f / B_);
    float var = s2 * (1.f / B_) - mu * mu;
    float sc  = rsqrtf(var + 1e-5f) * g[c];
    float bb  = b[c] - mu * sc;
    for (int r = 0; r < B_; r++)
        out[r * BNC + c] = v[r * BNC + c] * sc + bb;
}

// ---------------- small row GEMM: out[r,d] = A[r,:]@W + bias ----------------
template <int DIN>
__global__ void rows_gemm_bias(const float* __restrict__ A,
                               const float* __restrict__ W,
                               const float* __restrict__ bias,
                               float* __restrict__ out) {
    __shared__ float sA[16 * DIN];
    int r0 = blockIdx.x * 16;
    for (int idx = threadIdx.x; idx < 16 * DIN; idx += 128)
        sA[idx] = A[r0 * DIN + idx];
    __syncthreads();
    int d = threadIdx.x;
    float acc[16];
    float b0 = bias[d];
#pragma unroll
    for (int r = 0; r < 16; r++) acc[r] = b0;
    for (int k = 0; k < DIN; k++) {
        float w = W[k * D_ + d];
#pragma unroll
        for (int r = 0; r < 16; r++) acc[r] += sA[r * DIN + k] * w;
    }
#pragma unroll
    for (int r = 0; r < 16; r++) out[(r0 + r) * D_ + d] = acc[r];
}

// ---------------- fused edge layer via tensor cores (3xTF32) ----------------
// e_next[r,d] = relu( Ein[r,:]@W + eb[d] + ev[r>>6,d] + ev[b*64+(r&63),d] )
// RESID: Eout[r,d] = e_next + Ein[r,d]  (in place: Eout == Ein, stride 128)
// else:  Eout[r,d] = e_next             (Ein stride DIN, Eout stride 128)
template <int DIN, bool RESID>
__global__ void __launch_bounds__(256, 2) e_mma_kernel(
    const float* __restrict__ Ein, const float* __restrict__ W,
    const float* __restrict__ eb, const float* __restrict__ ev,
    float* __restrict__ Eout) {
    __shared__ float2 As2[8][132];   // [k][row] {hi, lo}
    __shared__ float2 Bs2[8][132];   // [k][col] {hi, lo}

    const int tid  = threadIdx.x;
    const int row0 = blockIdx.x * 128;
    const int lane = tid & 31, w = tid >> 5;
    const int wm = w & 3;        // 4 warps over rows  (32 rows each)
    const int wn = w >> 2;       // 2 warps over cols  (64 cols each)
    const int gq = lane >> 2, tq = lane & 3;

    float acc[2][8][4];
#pragma unroll
    for (int mf = 0; mf < 2; mf++)
#pragma unroll
        for (int nf = 0; nf < 8; nf++)
#pragma unroll
            for (int c = 0; c < 4; c++) acc[mf][nf][c] = 0.f;

    const int lr = tid >> 1, lh = (tid & 1) * 4;   // A loader: row / k-offset
    const int bk = tid >> 5, bc = (tid & 31) * 4;  // B loader: k-row / col

    float4 a_pre = *(const float4*)(Ein + (size_t)(row0 + lr) * DIN + lh);
    float4 b_pre = *(const float4*)(W + bk * D_ + bc);

    for (int k0 = 0; k0 < DIN; k0 += 8) {
        float4 a_cur = a_pre, b_cur = b_pre;
        if (k0 + 8 < DIN) {
            a_pre = *(const float4*)(Ein + (size_t)(row0 + lr) * DIN + k0 + 8 + lh);
            b_pre = *(const float4*)(W + (k0 + 8 + bk) * D_ + bc);
        }
        {
            float va[4] = {a_cur.x, a_cur.y, a_cur.z, a_cur.w};
#pragma unroll
            for (int q = 0; q < 4; q++) {
                float hi = tf32r(va[q]);
                As2[lh + q][lr] = make_float2(hi, va[q] - hi);
            }
            float vb[4] = {b_cur.x, b_cur.y, b_cur.z, b_cur.w};
#pragma unroll
            for (int q = 0; q < 4; q++) {
                float hi = tf32r(vb[q]);
                Bs2[bk][bc + q] = make_float2(hi, vb[q] - hi);
            }
        }
        __syncthreads();

        // A fragments for this warp (2 m-frags of 16 rows)
        unsigned ah[2][4], al[2][4];
#pragma unroll
        for (int mf = 0; mf < 2; mf++) {
            int r = wm * 32 + mf * 16 + gq;
            float2 t;
            t = As2[tq][r];         ah[mf][0] = __float_as_uint(t.x); al[mf][0] = __float_as_uint(t.y);
            t = As2[tq][r + 8];     ah[mf][1] = __float_as_uint(t.x); al[mf][1] = __float_as_uint(t.y);
            t = As2[tq + 4][r];     ah[mf][2] = __float_as_uint(t.x); al[mf][2] = __float_as_uint(t.y);
            t = As2[tq + 4][r + 8]; ah[mf][3] = __float_as_uint(t.x); al[mf][3] = __float_as_uint(t.y);
        }
#pragma unroll
        for (int nf = 0; nf < 8; nf++) {
            int c = wn * 64 + nf * 8 + gq;
            float2 t0 = Bs2[tq][c];
            float2 t1 = Bs2[tq + 4][c];
            unsigned bh0 = __float_as_uint(t0.x), bl0 = __float_as_uint(t0.y);
            unsigned bh1 = __float_as_uint(t1.x), bl1 = __float_as_uint(t1.y);
#pragma unroll
            for (int mf = 0; mf < 2; mf++) {
                mma8(acc[mf][nf], ah[mf], bh0, bh1);   // hi*hi
                mma8(acc[mf][nf], al[mf], bh0, bh1);   // lo*hi
                mma8(acc[mf][nf], ah[mf], bl0, bl1);   // hi*lo
            }
        }
        __syncthreads();
    }

    // ---------- epilogue ----------
    const int b = row0 >> 12;
    // ev for the i-vertex is constant across this warp's rows
    const float* evi = ev + ((row0 >> 6) + (wm >> 1)) * D_;
    float addc[8][2];
#pragma unroll
    for (int nf = 0; nf < 8; nf++) {
#pragma unroll
        for (int c = 0; c < 2; c++) {
            int d = wn * 64 + nf * 8 + tq * 2 + c;
            addc[nf][c] = eb[d] + evi[d];
        }
    }
#pragma unroll
    for (int mf = 0; mf < 2; mf++) {
#pragma unroll
        for (int h = 0; h < 2; h++) {
            int r = row0 + wm * 32 + mf * 16 + h * 8 + gq;
            const float* evj = ev + (b * N_ + (r & 63)) * D_;
#pragma unroll
            for (int nf = 0; nf < 8; nf++) {
                int d0 = wn * 64 + nf * 8 + tq * 2;
                float v0 = acc[mf][nf][h * 2 + 0] + addc[nf][0] + evj[d0];
                float v1 = acc[mf][nf][h * 2 + 1] + addc[nf][1] + evj[d0 + 1];
                v0 = fmaxf(v0, 0.f);
                v1 = fmaxf(v1, 0.f);
                if (RESID) {
                    float2 o = *(const float2*)(Ein + (size_t)r * D_ + d0);
                    v0 += o.x; v1 += o.y;
                }
                *(float2*)(Eout + (size_t)r * D_ + d0) = make_float2(v0, v1);
            }
        }
    }
}

// -------- sum over i + running-sum difference --------
// S_new[v,d] = sum_i E[b,i,j,d];  pve = DIFF ? S_new - S_old : S_new;  S_old <- S_new
template <bool DIFF>
__global__ void sum_diff_kernel(const float* __restrict__ E,
                                float* __restrict__ Ssave,
                                float* __restrict__ pve) {
    int idx = blockIdx.x * 256 + threadIdx.x;   // NV*D_ threads
    int d  = idx & 127;
    int bj = idx >> 7;
    int b  = bj >> 6, j = bj & 63;
    const float* base = E + (size_t)b * (N_ * N_ * D_) + j * D_ + d;
    float s = 0.f;
#pragma unroll 8
    for (int i = 0; i < N_; i++) s += base[(size_t)i * (N_ * D_)];
    pve[idx] = DIFF ? (s - Ssave[idx]) : s;
    Ssave[idx] = s;
}

// ---------------- vertex layer: concat([pve, vin]) @ vW + vb ----------------
template <int DVIN, bool RELU, bool RESID>
__global__ void v_layer_kernel(const float* __restrict__ pve,
                               const float* __restrict__ vin,
                               const float* __restrict__ vW,   // [(D_+DVIN), D_]
                               const float* __restrict__ vb,
                               const float* __restrict__ vres,
                               float* __restrict__ vout) {
    __shared__ float sP[16 * D_];
    __shared__ float sV[16 * DVIN];
    int r0 = blockIdx.x * 16;
    for (int idx = threadIdx.x; idx < 16 * D_; idx += 128) sP[idx] = pve[r0 * D_ + idx];
    for (int idx = threadIdx.x; idx < 16 * DVIN; idx += 128) sV[idx] = vin[r0 * DVIN + idx];
    __syncthreads();
    int d = threadIdx.x;
    float acc[16];
    float b0 = vb[d];
#pragma unroll
    for (int r = 0; r < 16; r++) acc[r] = b0;
    for (int k = 0; k < D_; k++) {
        float w = vW[k * D_ + d];
#pragma unroll
        for (int r = 0; r < 16; r++) acc[r] += sP[r * D_ + k] * w;
    }
    for (int k = 0; k < DVIN; k++) {
        float w = vW[(D_ + k) * D_ + d];
#pragma unroll
        for (int r = 0; r < 16; r++) acc[r] += sV[r * DVIN + k] * w;
    }
#pragma unroll
    for (int r = 0; r < 16; r++) {
        float val = acc[r];
        if (RELU) val = fmaxf(val, 0.f);
        if (RESID) val += vres[(r0 + r) * D_ + d];
        vout[(r0 + r) * D_ + d] = val;
    }
}

// ---------------- bn_inner: channels = n axis, stats over (B, D), eps=128 ----
__global__ void bn_inner_kernel(float* __restrict__ v,
                                const float* __restrict__ g,
                                const float* __restrict__ bb) {
    __shared__ float red[256], red2[256];
    int n = blockIdx.x;
    float s = 0.f, s2 = 0.f;
    for (int idx = threadIdx.x; idx < B_ * D_; idx += 256) {
        int batch = idx >> 7, d = idx & 127;
        float x = v[(batch * N_ + n) * D_ + d];
        s += x; s2 += x * x;
    }
    red[threadIdx.x] = s; red2[threadIdx.x] = s2;
    __syncthreads();
    for (int off = 128; off; off >>= 1) {
        if (threadIdx.x < off) {
            red[threadIdx.x]  += red[threadIdx.x + off];
            red2[threadIdx.x] += red2[threadIdx.x + off];
        }
        __syncthreads();
    }
    float mu  = red[0] * (1.f / (B_ * D_));
    float var = red2[0] * (1.f / (B_ * D_)) - mu * mu;
    float A   = rsqrtf(var + 128.f) * g[n];
    float Bc  = bb[n] - mu * A;
    for (int idx = threadIdx.x; idx < B_ * D_; idx += 256) {
        int batch = idx >> 7, d = idx & 127;
        int off = (batch * N_ + n) * D_ + d;
        v[off] = v[off] * A + Bc;
    }
}

// ---------------- final layer (output dims = 1) ----------------
__global__ void ev3_kernel(const float* __restrict__ v, const float* __restrict__ W,
                           const float* __restrict__ bias, float* __restrict__ out) {
    int gt = blockIdx.x * blockDim.x + threadIdx.x;
    int warp = gt >> 5, lane = gt & 31;
    if (warp >= NV) return;
    float4 x = *(const float4*)(v + warp * D_ + lane * 4);
    float4 ww = *(const float4*)(W + lane * 4);
    float s = x.x * ww.x + x.y * ww.y + x.z * ww.z + x.w * ww.w;
    for (int o = 16; o; o >>= 1) s += __shfl_xor_sync(0xffffffffu, s, o);
    if (lane == 0) out[warp] = s + bias[0];
}

__global__ void e3_kernel(const float* __restrict__ e, const float* __restrict__ W,
                          const float* __restrict__ bias, const float* __restrict__ ev3,
                          float* __restrict__ out) {
    int gt = blockIdx.x * blockDim.x + threadIdx.x;
    int warp = gt >> 5, lane = gt & 31;
    if (warp >= NE) return;
    float4 x = *(const float4*)(e + (size_t)warp * D_ + lane * 4);
    float4 ww = *(const float4*)(W + lane * 4);
    float s = x.x * ww.x + x.y * ww.y + x.z * ww.z + x.w * ww.w;
    for (int o = 16; o; o >>= 1) s += __shfl_xor_sync(0xffffffffu, s, o);
    if (lane == 0) {
        int b = warp >> 12, ii = (warp >> 6) & 63, jj = warp & 63;
        out[warp] = s + bias[0] + ev3[b * 64 + jj] + ev3[b * 64 + ii];
    }
}

__global__ void pve3_kernel(const float* __restrict__ e3, float* __restrict__ pve) {
    int idx = blockIdx.x * blockDim.x + threadIdx.x;
    if (idx >= NV) return;
    int b = idx >> 6, j = idx & 63;
    float s = 0.f;
#pragma unroll 8
    for (int i = 0; i < N_; i++) s += e3[(b * 64 + i) * 64 + j];
    pve[idx] = s;
}

__global__ void v3_kernel(const float* __restrict__ v, const float* __restrict__ pve3,
                          const float* __restrict__ W, const float* __restrict__ bias,
                          float* __restrict__ out) {
    int gt = blockIdx.x * blockDim.x + threadIdx.x;
    int warp = gt >> 5, lane = gt & 31;
    if (warp >= NV) return;
    const float* row = v + warp * D_;
    float s = 0.f;
    for (int k = lane; k < D_; k += 32) s += row[k] * W[1 + k];
    for (int o = 16; o; o >>= 1) s += __shfl_xor_sync(0xffffffffu, s, o);
    if (lane == 0) out[warp] = s + pve3[warp] * W[0] + bias[0];
}

// ---------------- host orchestration ----------------
extern "C" void kernel_launch(void* const* d_in, const int* in_sizes, int n_in,
                              void* d_out, int out_size) {
    const float* v_in    = (const float*)d_in[0];
    const float* e_in    = (const float*)d_in[1];
    const float* bn_in_g = (const float*)d_in[2];
    const float* bn_in_b = (const float*)d_in[3];
    const float* g1_evW  = (const float*)d_in[4];
    const float* g1_evb  = (const float*)d_in[5];
    const float* g1_eW   = (const float*)d_in[6];
    const float* g1_eb   = (const float*)d_in[7];
    const float* g1_vW   = (const float*)d_in[8];
    const float* g1_vb   = (const float*)d_in[9];
    const float* inn_evW = (const float*)d_in[10];
    const float* inn_evb = (const float*)d_in[11];
    const float* inn_eW  = (const float*)d_in[12];
    const float* inn_eb  = (const float*)d_in[13];
    const float* inn_vW  = (const float*)d_in[14];
    const float* inn_vb  = (const float*)d_in[15];
    const float* bn_g    = (const float*)d_in[16];
    const float* bn_b    = (const float*)d_in[17];
    const float* g3_evW  = (const float*)d_in[18];
    const float* g3_evb  = (const float*)d_in[19];
    const float* g3_eW   = (const float*)d_in[20];
    const float* g3_eb   = (const float*)d_in[21];
    const float* g3_vW   = (const float*)d_in[22];
    const float* g3_vb   = (const float*)d_in[23];
    float* out = (float*)d_out;

    float *pv0, *pv1, *pv2, *pev, *ppve, *pS, *peA, *pev3, *ppve3;
    cudaGetSymbolAddress((void**)&pv0,  g_v0);
    cudaGetSymbolAddress((void**)&pv1,  g_v1);
    cudaGetSymbolAddress((void**)&pv2,  g_v2);
    cudaGetSymbolAddress((void**)&pev,  g_ev);
    cudaGetSymbolAddress((void**)&ppve, g_pve);
    cudaGetSymbolAddress((void**)&pS,   g_S);
    cudaGetSymbolAddress((void**)&peA,  g_eA);
    cudaGetSymbolAddress((void**)&pev3, g_ev3);
    cudaGetSymbolAddress((void**)&ppve3, g_pve3);

    // input BN
    bn_flat_kernel<<<(BNC + 255) / 256, 256>>>(v_in, bn_in_g, bn_in_b, pv0);

    // layer 1
    rows_gemm_bias<VF_><<<NV / 16, 128>>>(pv0, g1_evW, g1_evb, pev);
    e_mma_kernel<EF_, false><<<NE / 128, 256>>>(e_in, g1_eW, g1_eb, pev, peA);
    sum_diff_kernel<false><<<NV * D_ / 256, 256>>>(peA, pS, ppve);
    v_layer_kernel<VF_, true, false><<<NV / 16, 128>>>(ppve, pv0, g1_vW, g1_vb, nullptr, pv1);

    // inner residual layers (e updated in place; pve = S_l - S_{l-1})
    float* vcur = pv1;
    float* vnxt = pv2;
    for (int l = 0; l < LN_; l++) {
        rows_gemm_bias<D_><<<NV / 16, 128>>>(vcur, inn_evW + l * D_ * D_, inn_evb + l * D_, pev);
        e_mma_kernel<D_, true><<<NE / 128, 256>>>(peA, inn_eW + l * D_ * D_,
                                                  inn_eb + l * D_, pev, peA);
        sum_diff_kernel<true><<<NV * D_ / 256, 256>>>(peA, pS, ppve);
        v_layer_kernel<D_, true, true><<<NV / 16, 128>>>(ppve, vcur, inn_vW + l * (2 * D_) * D_,
                                                         inn_vb + l * D_, vcur, vnxt);
        bn_inner_kernel<<<N_, 256>>>(vnxt, bn_g + l * N_, bn_b + l * N_);
        float* t = vcur; vcur = vnxt; vnxt = t;
    }

    // final layer (no relu), write directly into d_out: v [NV] then e [NE]
    ev3_kernel<<<NV * 32 / 256, 256>>>(vcur, g3_evW, g3_evb, pev3);
    e3_kernel<<<NE * 32 / 256, 256>>>(peA, g3_eW, g3_eb, pev3, out + NV);
    pve3_kernel<<<(NV + 255) / 256, 256>>>(out + NV, ppve3);
    v3_kernel<<<NV * 32 / 256, 256>>>(vcur, ppve3, g3_vW, g3_vb, out);
}

// round 3
// speedup vs baseline: 1.3153x; 1.1612x over previous
#include <cuda_runtime.h>
#include <cuda_bf16.h>

// ---------------- problem constants ----------------
#define B_  64
#define N_  64
#define VF_ 32
#define EF_ 16
#define D_  128
#define LN_ 4

constexpr int NV  = B_ * N_;        // 4096 vertices
constexpr int NE  = B_ * N_ * N_;   // 262144 edges
constexpr int BNC = N_ * VF_;       // 2048 bn_flat columns

// ---------------- device scratch (no allocation allowed) ----------------
__device__ float g_v0[NV * VF_];
__device__ float g_v1[NV * D_];
__device__ float g_v2[NV * D_];
__device__ float g_ev[NV * D_];
__device__ float g_pve[NV * D_];
__device__ float g_S[NV * D_];            // running sum_i of residual e-state
__device__ float g_eA[(size_t)NE * D_];   // e residual state (128 MB), updated in place
__device__ float g_ev3[NV];
__device__ float g_pve3[NV];

// ---------------- helpers ----------------
__device__ __forceinline__ unsigned pack2bf(float x, float y) {
    __nv_bfloat162 h = __floats2bfloat162_rn(x, y);
    return *(unsigned*)&h;
}

// split x into bf16 hi + bf16 lo (x ~= hi + lo, ~16 mantissa bits total)
__device__ __forceinline__ void split_bf(float x, float& hi, float& lo) {
    hi = __bfloat162float(__float2bfloat16_rn(x));
    lo = x - hi;
}

__device__ __forceinline__ void mma16(float* c, const unsigned* a, unsigned b0, unsigned b1) {
    asm volatile("mma.sync.aligned.m16n8k16.row.col.f32.bf16.bf16.f32 "
                 "{%0,%1,%2,%3}, {%4,%5,%6,%7}, {%8,%9}, {%0,%1,%2,%3};\n"
                 : "+f"(c[0]), "+f"(c[1]), "+f"(c[2]), "+f"(c[3])
                 : "r"(a[0]), "r"(a[1]), "r"(a[2]), "r"(a[3]), "r"(b0), "r"(b1));
}

// ---------------- bn_flat ----------------
__global__ void bn_flat_kernel(const float* __restrict__ v,
                               const float* __restrict__ g,
                               const float* __restrict__ b,
                               float* __restrict__ out) {
    int c = blockIdx.x * blockDim.x + threadIdx.x;
    if (c >= BNC) return;
    float s = 0.f, s2 = 0.f;
    for (int r = 0; r < B_; r++) {
        float x = v[r * BNC + c];
        s += x; s2 += x * x;
    }
    float mu  = s * (1.f / B_);
    float var = s2 * (1.f / B_) - mu * mu;
    float sc  = rsqrtf(var + 1e-5f) * g[c];
    float bb  = b[c] - mu * sc;
    for (int r = 0; r < B_; r++)
        out[r * BNC + c] = v[r * BNC + c] * sc + bb;
}

// ---------------- small row GEMM: out[r,d] = A[r,:]@W + bias ----------------
template <int DIN>
__global__ void rows_gemm_bias(const float* __restrict__ A,
                               const float* __restrict__ W,
                               const float* __restrict__ bias,
                               float* __restrict__ out) {
    __shared__ float sA[16 * DIN];
    int r0 = blockIdx.x * 16;
    for (int idx = threadIdx.x; idx < 16 * DIN; idx += 128)
        sA[idx] = A[r0 * DIN + idx];
    __syncthreads();
    int d = threadIdx.x;
    float acc[16];
    float b0 = bias[d];
#pragma unroll
    for (int r = 0; r < 16; r++) acc[r] = b0;
    for (int k = 0; k < DIN; k++) {
        float w = W[k * D_ + d];
#pragma unroll
        for (int r = 0; r < 16; r++) acc[r] += sA[r * DIN + k] * w;
    }
#pragma unroll
    for (int r = 0; r < 16; r++) out[(r0 + r) * D_ + d] = acc[r];
}

// ------------- fused edge layer: split-bf16 3-pass tensor-core GEMM -------------
// 128x128 tile, 512 threads (16 warps: 4 m-groups x 4 n-groups, warp = 32x32).
// e_next[r,d] = relu( Ein[r,:]@W + eb[d] + ev_i[d] + ev_j[d] ); optional += Ein (in place)
template <int DIN, bool RESID>
__global__ void __launch_bounds__(512, 1) e_mma_kernel(
    const float* __restrict__ Ein, const float* __restrict__ W,
    const float* __restrict__ eb, const float* __restrict__ ev,
    float* __restrict__ Eout) {

    // [kpair 0..7][row/col 0..127], bf16x2 packed (k even = low half)
    __shared__ unsigned sAh[8][136], sAl[8][136];
    __shared__ unsigned sBh[8][136], sBl[8][136];

    const int tid  = threadIdx.x;
    const int row0 = blockIdx.x * 128;
    const int lane = tid & 31, w = tid >> 5;
    const int wm = w & 3;         // 32-row group
    const int wn = w >> 2;        // 32-col group
    const int gq = lane >> 2, tq = lane & 3;

    float acc[2][4][4];
#pragma unroll
    for (int mf = 0; mf < 2; mf++)
#pragma unroll
        for (int nf = 0; nf < 4; nf++)
#pragma unroll
            for (int c = 0; c < 4; c++) acc[mf][nf][c] = 0.f;

    // A loader: row ar, k-pairs kpA, kpA+1 (one float4)
    const int ar  = tid >> 2;
    const int kpA = (tid & 3) * 2;
    // B loader: two items (kpB0,colB) and (kpB0+4,colB), two k-rows each
    const int kpB0 = tid >> 7;        // 0..3
    const int colB = tid & 127;

    constexpr int NCH = DIN / 16;

    float4 aP = *(const float4*)(Ein + (size_t)(row0 + ar) * DIN + kpA * 2);
    float w00 = W[(2 * kpB0) * D_ + colB];
    float w01 = W[(2 * kpB0 + 1) * D_ + colB];
    float w10 = W[(2 * (kpB0 + 4)) * D_ + colB];
    float w11 = W[(2 * (kpB0 + 4) + 1) * D_ + colB];

    for (int ch = 0; ch < NCH; ch++) {
        // convert prefetched data
        float ah0, al0, ah1, al1, ah2, al2, ah3, al3;
        split_bf(aP.x, ah0, al0); split_bf(aP.y, ah1, al1);
        split_bf(aP.z, ah2, al2); split_bf(aP.w, ah3, al3);
        float bh00, bl00, bh01, bl01, bh10, bl10, bh11, bl11;
        split_bf(w00, bh00, bl00); split_bf(w01, bh01, bl01);
        split_bf(w10, bh10, bl10); split_bf(w11, bh11, bl11);

        __syncthreads();   // previous chunk fully consumed
        sAh[kpA][ar]     = pack2bf(ah0, ah1);
        sAh[kpA + 1][ar] = pack2bf(ah2, ah3);
        sAl[kpA][ar]     = pack2bf(al0, al1);
        sAl[kpA + 1][ar] = pack2bf(al2, al3);
        sBh[kpB0][colB]     = pack2bf(bh00, bh01);
        sBl[kpB0][colB]     = pack2bf(bl00, bl01);
        sBh[kpB0 + 4][colB] = pack2bf(bh10, bh11);
        sBl[kpB0 + 4][colB] = pack2bf(bl10, bl11);
        __syncthreads();

        // prefetch next chunk (overlaps MMA below)
        if (ch + 1 < NCH) {
            int k0 = (ch + 1) * 16;
            aP = *(const float4*)(Ein + (size_t)(row0 + ar) * DIN + k0 + kpA * 2);
            w00 = W[(k0 + 2 * kpB0) * D_ + colB];
            w01 = W[(k0 + 2 * kpB0 + 1) * D_ + colB];
            w10 = W[(k0 + 2 * (kpB0 + 4)) * D_ + colB];
            w11 = W[(k0 + 2 * (kpB0 + 4) + 1) * D_ + colB];
        }

        // A fragments for both 16-row sub-tiles
        unsigned fah[2][4], fal[2][4];
#pragma unroll
        for (int mf = 0; mf < 2; mf++) {
            int r = wm * 32 + mf * 16 + gq;
            fah[mf][0] = sAh[tq][r];     fah[mf][1] = sAh[tq][r + 8];
            fah[mf][2] = sAh[tq + 4][r]; fah[mf][3] = sAh[tq + 4][r + 8];
            fal[mf][0] = sAl[tq][r];     fal[mf][1] = sAl[tq][r + 8];
            fal[mf][2] = sAl[tq + 4][r]; fal[mf][3] = sAl[tq + 4][r + 8];
        }
#pragma unroll
        for (int nf = 0; nf < 4; nf++) {
            int c = wn * 32 + nf * 8 + gq;
            unsigned bh0 = sBh[tq][c], bh1 = sBh[tq + 4][c];
            unsigned bl0 = sBl[tq][c], bl1 = sBl[tq + 4][c];
#pragma unroll
            for (int mf = 0; mf < 2; mf++) {
                mma16(acc[mf][nf], fah[mf], bh0, bh1);  // hi*hi
                mma16(acc[mf][nf], fal[mf], bh0, bh1);  // lo*hi
                mma16(acc[mf][nf], fah[mf], bl0, bl1);  // hi*lo
            }
        }
    }

    // ---------- epilogue: bias + ev_i + ev_j + relu (+ residual, in place) ----------
    const int b  = row0 >> 12;
    const int i0 = (row0 >> 6) & 63;
    const float* evi = ev + (size_t)(b * N_ + i0 + (wm >> 1)) * D_;

    float base[4][2];
#pragma unroll
    for (int nf = 0; nf < 4; nf++) {
        int d = wn * 32 + nf * 8 + tq * 2;
        base[nf][0] = eb[d] + evi[d];
        base[nf][1] = eb[d + 1] + evi[d + 1];
    }
#pragma unroll
    for (int mf = 0; mf < 2; mf++) {
#pragma unroll
        for (int h = 0; h < 2; h++) {
            int l = wm * 32 + mf * 16 + h * 8 + gq;
            int r = row0 + l;
            const float* evj = ev + (size_t)(b * N_ + (l & 63)) * D_;
#pragma unroll
            for (int nf = 0; nf < 4; nf++) {
                int d = wn * 32 + nf * 8 + tq * 2;
                float v0 = acc[mf][nf][h * 2 + 0] + base[nf][0] + evj[d];
                float v1 = acc[mf][nf][h * 2 + 1] + base[nf][1] + evj[d + 1];
                v0 = fmaxf(v0, 0.f);
                v1 = fmaxf(v1, 0.f);
                if (RESID) {
                    float2 o = *(const float2*)(Ein + (size_t)r * D_ + d);
                    v0 += o.x; v1 += o.y;
                }
                *(float2*)(Eout + (size_t)r * D_ + d) = make_float2(v0, v1);
            }
        }
    }
}

// -------- sum over i + running-sum difference --------
template <bool DIFF>
__global__ void sum_diff_kernel(const float* __restrict__ E,
                                float* __restrict__ Ssave,
                                float* __restrict__ pve) {
    int idx = blockIdx.x * 256 + threadIdx.x;   // NV*D_ threads
    int d  = idx & 127;
    int bj = idx >> 7;
    int b  = bj >> 6, j = bj & 63;
    const float* base = E + (size_t)b * (N_ * N_ * D_) + j * D_ + d;
    float s = 0.f;
#pragma unroll 16
    for (int i = 0; i < N_; i++) s += base[(size_t)i * (N_ * D_)];
    pve[idx] = DIFF ? (s - Ssave[idx]) : s;
    Ssave[idx] = s;
}

// ---------------- vertex layer: concat([pve, vin]) @ vW + vb ----------------
template <int DVIN, bool RELU, bool RESID>
__global__ void v_layer_kernel(const float* __restrict__ pve,
                               const float* __restrict__ vin,
                               const float* __restrict__ vW,   // [(D_+DVIN), D_]
                               const float* __restrict__ vb,
                               const float* __restrict__ vres,
                               float* __restrict__ vout) {
    __shared__ float sP[16 * D_];
    __shared__ float sV[16 * DVIN];
    int r0 = blockIdx.x * 16;
    for (int idx = threadIdx.x; idx < 16 * D_; idx += 128) sP[idx] = pve[r0 * D_ + idx];
    for (int idx = threadIdx.x; idx < 16 * DVIN; idx += 128) sV[idx] = vin[r0 * DVIN + idx];
    __syncthreads();
    int d = threadIdx.x;
    float acc[16];
    float b0 = vb[d];
#pragma unroll
    for (int r = 0; r < 16; r++) acc[r] = b0;
    for (int k = 0; k < D_; k++) {
        float w = vW[k * D_ + d];
#pragma unroll
        for (int r = 0; r < 16; r++) acc[r] += sP[r * D_ + k] * w;
    }
    for (int k = 0; k < DVIN; k++) {
        float w = vW[(D_ + k) * D_ + d];
#pragma unroll
        for (int r = 0; r < 16; r++) acc[r] += sV[r * DVIN + k] * w;
    }
#pragma unroll
    for (int r = 0; r < 16; r++) {
        float val = acc[r];
        if (RELU) val = fmaxf(val, 0.f);
        if (RESID) val += vres[(r0 + r) * D_ + d];
        vout[(r0 + r) * D_ + d] = val;
    }
}

// ---------------- bn_inner: channels = n axis, stats over (B, D), eps=128 ----
__global__ void bn_inner_kernel(float* __restrict__ v,
                                const float* __restrict__ g,
                                const float* __restrict__ bb) {
    __shared__ float red[256], red2[256];
    int n = blockIdx.x;
    float s = 0.f, s2 = 0.f;
    for (int idx = threadIdx.x; idx < B_ * D_; idx += 256) {
        int batch = idx >> 7, d = idx & 127;
        float x = v[(batch * N_ + n) * D_ + d];
        s += x; s2 += x * x;
    }
    red[threadIdx.x] = s; red2[threadIdx.x] = s2;
    __syncthreads();
    for (int off = 128; off; off >>= 1) {
        if (threadIdx.x < off) {
            red[threadIdx.x]  += red[threadIdx.x + off];
            red2[threadIdx.x] += red2[threadIdx.x + off];
        }
        __syncthreads();
    }
    float mu  = red[0] * (1.f / (B_ * D_));
    float var = red2[0] * (1.f / (B_ * D_)) - mu * mu;
    float A   = rsqrtf(var + 128.f) * g[n];
    float Bc  = bb[n] - mu * A;
    for (int idx = threadIdx.x; idx < B_ * D_; idx += 256) {
        int batch = idx >> 7, d = idx & 127;
        int off = (batch * N_ + n) * D_ + d;
        v[off] = v[off] * A + Bc;
    }
}

// ---------------- final layer (output dims = 1) ----------------
__global__ void ev3_kernel(const float* __restrict__ v, const float* __restrict__ W,
                           const float* __restrict__ bias, float* __restrict__ out) {
    int gt = blockIdx.x * blockDim.x + threadIdx.x;
    int warp = gt >> 5, lane = gt & 31;
    if (warp >= NV) return;
    float4 x = *(const float4*)(v + warp * D_ + lane * 4);
    float4 ww = *(const float4*)(W + lane * 4);
    float s = x.x * ww.x + x.y * ww.y + x.z * ww.z + x.w * ww.w;
    for (int o = 16; o; o >>= 1) s += __shfl_xor_sync(0xffffffffu, s, o);
    if (lane == 0) out[warp] = s + bias[0];
}

__global__ void e3_kernel(const float* __restrict__ e, const float* __restrict__ W,
                          const float* __restrict__ bias, const float* __restrict__ ev3,
                          float* __restrict__ out) {
    int gt = blockIdx.x * blockDim.x + threadIdx.x;
    int warp = gt >> 5, lane = gt & 31;
    if (warp >= NE) return;
    float4 x = *(const float4*)(e + (size_t)warp * D_ + lane * 4);
    float4 ww = *(const float4*)(W + lane * 4);
    float s = x.x * ww.x + x.y * ww.y + x.z * ww.z + x.w * ww.w;
    for (int o = 16; o; o >>= 1) s += __shfl_xor_sync(0xffffffffu, s, o);
    if (lane == 0) {
        int b = warp >> 12, ii = (warp >> 6) & 63, jj = warp & 63;
        out[warp] = s + bias[0] + ev3[b * 64 + jj] + ev3[b * 64 + ii];
    }
}

__global__ void pve3_kernel(const float* __restrict__ e3, float* __restrict__ pve) {
    int idx = blockIdx.x * blockDim.x + threadIdx.x;
    if (idx >= NV) return;
    int b = idx >> 6, j = idx & 63;
    float s = 0.f;
#pragma unroll 8
    for (int i = 0; i < N_; i++) s += e3[(b * 64 + i) * 64 + j];
    pve[idx] = s;
}

__global__ void v3_kernel(const float* __restrict__ v, const float* __restrict__ pve3,
                          const float* __restrict__ W, const float* __restrict__ bias,
                          float* __restrict__ out) {
    int gt = blockIdx.x * blockDim.x + threadIdx.x;
    int warp = gt >> 5, lane = gt & 31;
    if (warp >= NV) return;
    const float* row = v + warp * D_;
    float s = 0.f;
    for (int k = lane; k < D_; k += 32) s += row[k] * W[1 + k];
    for (int o = 16; o; o >>= 1) s += __shfl_xor_sync(0xffffffffu, s, o);
    if (lane == 0) out[warp] = s + pve3[warp] * W[0] + bias[0];
}

// ---------------- host orchestration ----------------
extern "C" void kernel_launch(void* const* d_in, const int* in_sizes, int n_in,
                              void* d_out, int out_size) {
    const float* v_in    = (const float*)d_in[0];
    const float* e_in    = (const float*)d_in[1];
    const float* bn_in_g = (const float*)d_in[2];
    const float* bn_in_b = (const float*)d_in[3];
    const float* g1_evW  = (const float*)d_in[4];
    const float* g1_evb  = (const float*)d_in[5];
    const float* g1_eW   = (const float*)d_in[6];
    const float* g1_eb   = (const float*)d_in[7];
    const float* g1_vW   = (const float*)d_in[8];
    const float* g1_vb   = (const float*)d_in[9];
    const float* inn_evW = (const float*)d_in[10];
    const float* inn_evb = (const float*)d_in[11];
    const float* inn_eW  = (const float*)d_in[12];
    const float* inn_eb  = (const float*)d_in[13];
    const float* inn_vW  = (const float*)d_in[14];
    const float* inn_vb  = (const float*)d_in[15];
    const float* bn_g    = (const float*)d_in[16];
    const float* bn_b    = (const float*)d_in[17];
    const float* g3_evW  = (const float*)d_in[18];
    const float* g3_evb  = (const float*)d_in[19];
    const float* g3_eW   = (const float*)d_in[20];
    const float* g3_eb   = (const float*)d_in[21];
    const float* g3_vW   = (const float*)d_in[22];
    const float* g3_vb   = (const float*)d_in[23];
    float* out = (float*)d_out;

    float *pv0, *pv1, *pv2, *pev, *ppve, *pS, *peA, *pev3, *ppve3;
    cudaGetSymbolAddress((void**)&pv0,  g_v0);
    cudaGetSymbolAddress((void**)&pv1,  g_v1);
    cudaGetSymbolAddress((void**)&pv2,  g_v2);
    cudaGetSymbolAddress((void**)&pev,  g_ev);
    cudaGetSymbolAddress((void**)&ppve, g_pve);
    cudaGetSymbolAddress((void**)&pS,   g_S);
    cudaGetSymbolAddress((void**)&peA,  g_eA);
    cudaGetSymbolAddress((void**)&pev3, g_ev3);
    cudaGetSymbolAddress((void**)&ppve3, g_pve3);

    // input BN
    bn_flat_kernel<<<(BNC + 255) / 256, 256>>>(v_in, bn_in_g, bn_in_b, pv0);

    // layer 1
    rows_gemm_bias<VF_><<<NV / 16, 128>>>(pv0, g1_evW, g1_evb, pev);
    e_mma_kernel<EF_, false><<<NE / 128, 512>>>(e_in, g1_eW, g1_eb, pev, peA);
    sum_diff_kernel<false><<<NV * D_ / 256, 256>>>(peA, pS, ppve);
    v_layer_kernel<VF_, true, false><<<NV / 16, 128>>>(ppve, pv0, g1_vW, g1_vb, nullptr, pv1);

    // inner residual layers (e updated in place; pve = S_l - S_{l-1})
    float* vcur = pv1;
    float* vnxt = pv2;
    for (int l = 0; l < LN_; l++) {
        rows_gemm_bias<D_><<<NV / 16, 128>>>(vcur, inn_evW + l * D_ * D_, inn_evb + l * D_, pev);
        e_mma_kernel<D_, true><<<NE / 128, 512>>>(peA, inn_eW + l * D_ * D_,
                                                  inn_eb + l * D_, pev, peA);
        sum_diff_kernel<true><<<NV * D_ / 256, 256>>>(peA, pS, ppve);
        v_layer_kernel<D_, true, true><<<NV / 16, 128>>>(ppve, vcur, inn_vW + l * (2 * D_) * D_,
                                                         inn_vb + l * D_, vcur, vnxt);
        bn_inner_kernel<<<N_, 256>>>(vnxt, bn_g + l * N_, bn_b + l * N_);
        float* t = vcur; vcur = vnxt; vnxt = t;
    }

    // final layer (no relu), write directly into d_out: v [NV] then e [NE]
    ev3_kernel<<<NV * 32 / 256, 256>>>(vcur, g3_evW, g3_evb, pev3);
    e3_kernel<<<NE * 32 / 256, 256>>>(peA, g3_eW, g3_eb, pev3, out + NV);
    pve3_kernel<<<(NV + 255) / 256, 256>>>(out + NV, ppve3);
    v3_kernel<<<NV * 32 / 256, 256>>>(vcur, ppve3, g3_vW, g3_vb, out);
}